// round 5
// baseline (speedup 1.0000x reference)
#include <cuda_runtime.h>
#include <math.h>

// Problem constants: B=2, S=2048, DM=1024, H=16, HKV=4, HD=64, REP=4, THETA=10000

typedef unsigned long long u64;

// ---------------- packed f32x2 helpers (FFMA2 path, sm_100+) --------------
__device__ __forceinline__ u64 pack2(float v) {
    u64 r; asm("mov.b64 %0,{%1,%1};" : "=l"(r) : "f"(v)); return r;
}
__device__ __forceinline__ void fma2(u64& d, u64 a, u64 b) {
    asm("fma.rn.f32x2 %0,%1,%2,%0;" : "+l"(d) : "l"(a), "l"(b));
}
__device__ __forceinline__ void mul2(u64& d, u64 a) {
    asm("mul.rn.f32x2 %0,%0,%1;" : "+l"(d) : "l"(a));
}
__device__ __forceinline__ float2 unpack2(u64 v) {
    float2 f; asm("mov.b64 {%0,%1},%2;" : "=f"(f.x), "=f"(f.y) : "l"(v)); return f;
}

// ---------------- device scratch (no allocation allowed) ----------------
__device__ float g_Q[2 * 16 * 2048 * 64];   // [B,H,S,HD]
__device__ float g_K[2 * 4 * 2048 * 64];    // [B,HKV,S,HD]
__device__ float g_V[2 * 4 * 2048 * 64];    // [B,HKV,S,HD]
__device__ float g_att[2 * 2048 * 1024];    // [B,S,H*HD]

// =========================================================================
// Tiled fp32 GEMM: Y = X @ W.  X:[4096,1024], W:[1024,N].
// NH > 0 : scatter output column n -> head h=n/64, Y layout [B,NH,S,64]
// NH == 0: plain row-major Y [4096,1024]
// Block: 256 threads (16x16), tile 64x64, k-step 16, 4x4 micro-tile,
// inner product via packed fma.rn.f32x2 (2 MACs / FMA-pipe slot).
// =========================================================================
template <int NH>
__global__ __launch_bounds__(256)
void gemm_kernel(const float* __restrict__ X, const float* __restrict__ W,
                 float* __restrict__ Y, int N) {
    __shared__ float As[16][68];  // A transposed: [k][m]  (68*4B = 272B rows, 16B-aligned)
    __shared__ float Bs[16][68];  // [k][n]

    const int tid = threadIdx.x;
    const int tx = tid & 15, ty = tid >> 4;
    const int m0 = blockIdx.y * 64;
    const int n0 = blockIdx.x * 64;

    const int arow = tid >> 2,  akc = (tid & 3) * 4;    // A loader
    const int brow = tid >> 4,  bnc = (tid & 15) * 4;   // B loader

    u64 acc[4][2];
#pragma unroll
    for (int i = 0; i < 4; ++i) { acc[i][0] = 0ull; acc[i][1] = 0ull; }

    for (int k0 = 0; k0 < 1024; k0 += 16) {
        float4 a = *(const float4*)&X[(size_t)(m0 + arow) * 1024 + k0 + akc];
        As[akc + 0][arow] = a.x;
        As[akc + 1][arow] = a.y;
        As[akc + 2][arow] = a.z;
        As[akc + 3][arow] = a.w;
        *(float4*)&Bs[brow][bnc] =
            *(const float4*)&W[(size_t)(k0 + brow) * N + n0 + bnc];
        __syncthreads();

#pragma unroll
        for (int kk = 0; kk < 16; ++kk) {
            float4 av = *(float4*)&As[kk][4 * ty];
            const u64* bp = (const u64*)&Bs[kk][4 * tx];
            u64 b0 = bp[0], b1 = bp[1];
            u64 a0 = pack2(av.x), a1 = pack2(av.y);
            u64 a2 = pack2(av.z), a3 = pack2(av.w);
            fma2(acc[0][0], a0, b0); fma2(acc[0][1], a0, b1);
            fma2(acc[1][0], a1, b0); fma2(acc[1][1], a1, b1);
            fma2(acc[2][0], a2, b0); fma2(acc[2][1], a2, b1);
            fma2(acc[3][0], a3, b0); fma2(acc[3][1], a3, b1);
        }
        __syncthreads();
    }

#pragma unroll
    for (int i = 0; i < 4; ++i) {
        const int r = m0 + 4 * ty + i;
        float2 lo = unpack2(acc[i][0]);
        float2 hi = unpack2(acc[i][1]);
        float4 v = make_float4(lo.x, lo.y, hi.x, hi.y);
        if constexpr (NH > 0) {
            const int b = r >> 11;        // r / 2048
            const int sidx = r & 2047;    // r % 2048
            *(float4*)&Y[(((size_t)(b * NH + blockIdx.x)) * 2048 + sidx) * 64 +
                         4 * tx] = v;
        } else {
            *(float4*)&Y[(size_t)r * 1024 + n0 + 4 * tx] = v;
        }
    }
}

// =========================================================================
// Continuous 2D RoPE over T:[B*NH, S, 64].  One thread per (bh, s, pair p).
// =========================================================================
__global__ __launch_bounds__(256)
void rope_kernel(float* __restrict__ T, const float* __restrict__ pos) {
    const int idx = blockIdx.x * blockDim.x + threadIdx.x;
    const int p  = idx & 15;
    const int s  = (idx >> 4) & 2047;
    const int bh = idx >> 15;

    // 10000^(-p/16) = exp2(-p * log2(10000)/16)
    const float inv = exp2f((float)p * (-13.287712379549449f / 16.0f));
    const float cx = pos[2 * s];
    const float cy = pos[2 * s + 1];
    float sinx, cosx, siny, cosy;
    sincosf(cx * inv, &sinx, &cosx);
    sincosf(cy * inv, &siny, &cosy);

    float* base = T + ((size_t)bh * 2048 + s) * 64;

    float a0 = base[2 * p], a1 = base[2 * p + 1];
    base[2 * p]     = a0 * cosx - a1 * sinx;
    base[2 * p + 1] = a1 * cosx + a0 * sinx;

    float b0 = base[32 + 2 * p], b1 = base[33 + 2 * p];
    base[32 + 2 * p] = b0 * cosy - b1 * siny;
    base[33 + 2 * p] = b1 * cosy + b0 * siny;
}

// =========================================================================
// Flash attention (non-causal, full softmax), fp32 with f32x2 packed FMA.
// Grid: (S/64, B*H). Block: 256 threads (16x16).
// =========================================================================
#define SMEM_ATTN ((3 * 64 * 64 + 64 * 68) * 4)  // Qs,Vs,Ps (64x64) + KsT (64x68)

__global__ __launch_bounds__(256)
void attn_kernel(const float* __restrict__ Q, const float* __restrict__ K,
                 const float* __restrict__ V, float* __restrict__ Oa) {
    extern __shared__ float sm[];
    float* Qs  = sm;                 // [64 q][64 d]
    float* Vs  = Qs + 64 * 64;       // [64 k][64 d]
    float* Ps  = Vs + 64 * 64;       // [64 q][64 k]
    float* KsT = Ps + 64 * 64;       // [64 d][68]  (d-major, padded; 272B rows)

    const int tid = threadIdx.x;
    const int tx = tid & 15, ty = tid >> 4;
    const int qt = blockIdx.x * 64;
    const int bh = blockIdx.y;            // b*16 + h
    const int b = bh >> 4, h = bh & 15;
    const int hkv = h >> 2;               // GQA: 4 query heads per kv head

    const float* Qg = Q + (((size_t)bh) * 2048 + qt) * 64;
    const float* Kg = K + ((size_t)(b * 4 + hkv)) * 2048 * 64;
    const float* Vg = V + ((size_t)(b * 4 + hkv)) * 2048 * 64;

    const int lr = tid >> 4;              // 0..15
    const int lc = (tid & 15) * 4;        // 0..60

    // Load Q tile
#pragma unroll
    for (int r = 0; r < 4; ++r) {
        const int row = r * 16 + lr;
        *(float4*)&Qs[row * 64 + lc] = *(const float4*)&Qg[row * 64 + lc];
    }

    float m[4], l[4];
    u64 op[4][2];
#pragma unroll
    for (int i = 0; i < 4; ++i) {
        m[i] = -1e30f;
        l[i] = 0.0f;
        op[i][0] = 0ull; op[i][1] = 0ull;
    }
    __syncthreads();

    for (int kt = 0; kt < 2048; kt += 64) {
        // Load K tile transposed (d-major) and V tile
#pragma unroll
        for (int r = 0; r < 4; ++r) {
            const int row = r * 16 + lr;
            float4 kv = *(const float4*)&Kg[(size_t)(kt + row) * 64 + lc];
            KsT[(lc + 0) * 68 + row] = kv.x;
            KsT[(lc + 1) * 68 + row] = kv.y;
            KsT[(lc + 2) * 68 + row] = kv.z;
            KsT[(lc + 3) * 68 + row] = kv.w;
            *(float4*)&Vs[row * 64 + lc] =
                *(const float4*)&Vg[(size_t)(kt + row) * 64 + lc];
        }
        __syncthreads();

        // S = Q @ K^T  (4x4 micro-tile, packed f32x2)
        u64 sp[4][2];
#pragma unroll
        for (int i = 0; i < 4; ++i) { sp[i][0] = 0ull; sp[i][1] = 0ull; }

#pragma unroll 16
        for (int d = 0; d < 64; ++d) {
            const u64* kp2 = (const u64*)&KsT[d * 68 + 4 * tx];
            u64 k0 = kp2[0], k1 = kp2[1];
            u64 q0 = pack2(Qs[(4 * ty + 0) * 64 + d]);
            u64 q1 = pack2(Qs[(4 * ty + 1) * 64 + d]);
            u64 q2 = pack2(Qs[(4 * ty + 2) * 64 + d]);
            u64 q3 = pack2(Qs[(4 * ty + 3) * 64 + d]);
            fma2(sp[0][0], q0, k0); fma2(sp[0][1], q0, k1);
            fma2(sp[1][0], q1, k0); fma2(sp[1][1], q1, k1);
            fma2(sp[2][0], q2, k0); fma2(sp[2][1], q2, k1);
            fma2(sp[3][0], q3, k0); fma2(sp[3][1], q3, k1);
        }

        // Online softmax update (rows owned by ty; reduce across 16 tx lanes)
        const float scale = 0.125f;  // 1/sqrt(64)
#pragma unroll
        for (int i = 0; i < 4; ++i) {
            float2 slo = unpack2(sp[i][0]);
            float2 shi = unpack2(sp[i][1]);
            float s0 = slo.x * scale, s1 = slo.y * scale;
            float s2 = shi.x * scale, s3 = shi.y * scale;
            float mx = fmaxf(fmaxf(s0, s1), fmaxf(s2, s3));
            mx = fmaxf(mx, __shfl_xor_sync(0xffffffffu, mx, 1));
            mx = fmaxf(mx, __shfl_xor_sync(0xffffffffu, mx, 2));
            mx = fmaxf(mx, __shfl_xor_sync(0xffffffffu, mx, 4));
            mx = fmaxf(mx, __shfl_xor_sync(0xffffffffu, mx, 8));
            const float mn = fmaxf(m[i], mx);
            const float alpha = __expf(m[i] - mn);
            m[i] = mn;
            s0 = __expf(s0 - mn); s1 = __expf(s1 - mn);
            s2 = __expf(s2 - mn); s3 = __expf(s3 - mn);
            float rs = s0 + s1 + s2 + s3;
            rs += __shfl_xor_sync(0xffffffffu, rs, 1);
            rs += __shfl_xor_sync(0xffffffffu, rs, 2);
            rs += __shfl_xor_sync(0xffffffffu, rs, 4);
            rs += __shfl_xor_sync(0xffffffffu, rs, 8);
            l[i] = l[i] * alpha + rs;
            u64 ap = pack2(alpha);
            mul2(op[i][0], ap);
            mul2(op[i][1], ap);
            *(float4*)&Ps[(4 * ty + i) * 64 + 4 * tx] =
                make_float4(s0, s1, s2, s3);
        }
        __syncthreads();

        // O += P @ V  (packed f32x2)
#pragma unroll 16
        for (int k = 0; k < 64; ++k) {
            const u64* vp2 = (const u64*)&Vs[k * 64 + 4 * tx];
            u64 v0 = vp2[0], v1 = vp2[1];
            u64 p0 = pack2(Ps[(4 * ty + 0) * 64 + k]);
            u64 p1 = pack2(Ps[(4 * ty + 1) * 64 + k]);
            u64 p2 = pack2(Ps[(4 * ty + 2) * 64 + k]);
            u64 p3 = pack2(Ps[(4 * ty + 3) * 64 + k]);
            fma2(op[0][0], p0, v0); fma2(op[0][1], p0, v1);
            fma2(op[1][0], p1, v0); fma2(op[1][1], p1, v1);
            fma2(op[2][0], p2, v0); fma2(op[2][1], p2, v1);
            fma2(op[3][0], p3, v0); fma2(op[3][1], p3, v1);
        }
        __syncthreads();
    }

    // Epilogue: normalize and write to [B, S, H*64]
#pragma unroll
    for (int i = 0; i < 4; ++i) {
        const float invl = 1.0f / l[i];
        const int srow = qt + 4 * ty + i;
        float2 lo = unpack2(op[i][0]);
        float2 hi = unpack2(op[i][1]);
        float4 r = make_float4(lo.x * invl, lo.y * invl,
                               hi.x * invl, hi.y * invl);
        *(float4*)&Oa[((size_t)(b * 2048 + srow)) * 1024 + h * 64 + 4 * tx] = r;
    }
}

// =========================================================================
// Launch
// =========================================================================
extern "C" void kernel_launch(void* const* d_in, const int* in_sizes, int n_in,
                              void* d_out, int out_size) {
    (void)in_sizes; (void)n_in; (void)out_size;
    const float* x   = (const float*)d_in[0];
    const float* pos = (const float*)d_in[1];
    const float* Wq  = (const float*)d_in[2];
    const float* Wk  = (const float*)d_in[3];
    const float* Wv  = (const float*)d_in[4];
    const float* Wo  = (const float*)d_in[5];
    float* out = (float*)d_out;

    float *qp, *kp, *vp, *ap;
    cudaGetSymbolAddress((void**)&qp, g_Q);
    cudaGetSymbolAddress((void**)&kp, g_K);
    cudaGetSymbolAddress((void**)&vp, g_V);
    cudaGetSymbolAddress((void**)&ap, g_att);

    // QKV projections (scattered into per-head layouts)
    gemm_kernel<16><<<dim3(16, 64), 256>>>(x, Wq, qp, 1024);
    gemm_kernel<4><<<dim3(4, 64), 256>>>(x, Wk, kp, 256);
    gemm_kernel<4><<<dim3(4, 64), 256>>>(x, Wv, vp, 256);

    // RoPE on Q (B*H*S*16 threads) and K (B*HKV*S*16 threads)
    rope_kernel<<<4096, 256>>>(qp, pos);
    rope_kernel<<<1024, 256>>>(kp, pos);

    // Flash attention
    cudaFuncSetAttribute(attn_kernel, cudaFuncAttributeMaxDynamicSharedMemorySize,
                         SMEM_ATTN);
    attn_kernel<<<dim3(32, 32), 256, SMEM_ATTN>>>(qp, kp, vp, ap);

    // Output projection
    gemm_kernel<0><<<dim3(16, 64), 256>>>(ap, Wo, out, 1024);
}